// round 6
// baseline (speedup 1.0000x reference)
#include <cuda_runtime.h>
#include <cstdint>

// LIF recurrence over 4 timesteps (forward value only):
//   mem = 0.25*mem + x[t]; spike = mem > 0.5; out[t] = spike; mem = spike ? 0 : mem
//
// x/out: [T=4, N=8388608] fp32. Streaming 1R:1W, 268 MB total -> HBM-bound.
// R5: persistent grid-stride kernel (single wave, no wave-transition cost),
// front-batched loads (MLP=4/thread), .cs loads (zero reuse) + DEFAULT stores
// (let L2 batch writebacks lazily instead of evict-first).

static constexpr float DECAY  = 0.25f;
static constexpr float THRESH = 0.5f;   // V_TH=1: mem/V_TH > 0.5 <=> mem > 0.5

__device__ __forceinline__ void lif_step(float& mem, const float x, float& sp) {
    mem = fmaf(mem, DECAY, x);
    bool s = mem > THRESH;
    sp  = s ? 1.f : 0.f;
    mem = s ? 0.f : mem;
}

__device__ __forceinline__ void lif_step4(float4& mem, float4& io) {
    lif_step(mem.x, io.x, io.x);
    lif_step(mem.y, io.y, io.y);
    lif_step(mem.z, io.z, io.z);
    lif_step(mem.w, io.w, io.w);
}

__global__ __launch_bounds__(256)
void lif_kernel(const float4* __restrict__ x, float4* __restrict__ out, int n4) {
    const int stride = gridDim.x * blockDim.x;

    for (int i = blockIdx.x * blockDim.x + threadIdx.x; i < n4; i += stride) {
        // ---- read phase: 4 independent LDG.128 in flight ----
        float4 v0 = __ldcs(x + (size_t)0 * n4 + i);
        float4 v1 = __ldcs(x + (size_t)1 * n4 + i);
        float4 v2 = __ldcs(x + (size_t)2 * n4 + i);
        float4 v3 = __ldcs(x + (size_t)3 * n4 + i);

        // ---- compute ----
        float4 mem = make_float4(0.f, 0.f, 0.f, 0.f);
        lif_step4(mem, v0);
        lif_step4(mem, v1);
        lif_step4(mem, v2);
        lif_step4(mem, v3);

        // ---- write phase: default stores (lazy L2 writeback batching) ----
        out[(size_t)0 * n4 + i] = v0;
        out[(size_t)1 * n4 + i] = v1;
        out[(size_t)2 * n4 + i] = v2;
        out[(size_t)3 * n4 + i] = v3;
    }
}

extern "C" void kernel_launch(void* const* d_in, const int* in_sizes, int n_in,
                              void* d_out, int out_size) {
    const float* x = (const float*)d_in[0];
    float* out = (float*)d_out;

    const int total = in_sizes[0];          // T*N = 33,554,432
    const int n = total / 4;                // N per timestep
    const int n4 = n / 4;                   // float4 groups per timestep

    // Persistent single-wave grid: sm_100a has 148 SMs; at ~28-32 regs/thread
    // and 256 threads/block we fit 8 blocks/SM (64 warps, occupancy cap).
    const int threads = 256;
    const int blocks = 148 * 8;             // 1184 blocks = one full wave

    lif_kernel<<<blocks, threads>>>((const float4*)x, (float4*)out, n4);
}

// round 7
// speedup vs baseline: 1.1357x; 1.1357x over previous
#include <cuda_runtime.h>
#include <cstdint>

// LIF recurrence over 4 timesteps (forward value only):
//   mem = 0.25*mem + x[t]; spike = mem > 0.5; out[t] = spike; mem = spike ? 0 : mem
//
// x/out: [T=4, N=8388608] fp32. Pure 1R:1W stream, 268 MB -> HBM-bound.
// R6: combine R3's high occupancy (ILP=1, ~26 regs, 8 blocks/SM) with R4's
// phase structure (front-batched .cs loads, batched .cs stores). .cs on BOTH
// paths: R5 showed default (.wb) stores regress DRAM eff by ~6% (L2 writeback
// bursts colliding with the read stream); evict-first stores smooth turnaround.

static constexpr float DECAY  = 0.25f;
static constexpr float THRESH = 0.5f;   // V_TH=1: mem/V_TH > 0.5 <=> mem > 0.5

__device__ __forceinline__ void lif_step(float& mem, const float x, float& sp) {
    mem = fmaf(mem, DECAY, x);
    bool s = mem > THRESH;
    sp  = s ? 1.f : 0.f;
    mem = s ? 0.f : mem;
}

__device__ __forceinline__ void lif_step4(float4& mem, float4& io /* in: x, out: spike */) {
    lif_step(mem.x, io.x, io.x);
    lif_step(mem.y, io.y, io.y);
    lif_step(mem.z, io.z, io.z);
    lif_step(mem.w, io.w, io.w);
}

__global__ __launch_bounds__(256)
void lif_kernel(const float4* __restrict__ x, float4* __restrict__ out, int n4) {
    const int i = blockIdx.x * blockDim.x + threadIdx.x;
    if (i >= n4) return;

    // ---- read phase: 4 independent LDG.128 in flight per thread ----
    float4 v0 = __ldcs(x + (size_t)0 * n4 + i);
    float4 v1 = __ldcs(x + (size_t)1 * n4 + i);
    float4 v2 = __ldcs(x + (size_t)2 * n4 + i);
    float4 v3 = __ldcs(x + (size_t)3 * n4 + i);

    // ---- compute: sequential recurrence in registers ----
    float4 mem = make_float4(0.f, 0.f, 0.f, 0.f);
    lif_step4(mem, v0);
    lif_step4(mem, v1);
    lif_step4(mem, v2);
    lif_step4(mem, v3);

    // ---- write phase: batched evict-first stores ----
    __stcs(out + (size_t)0 * n4 + i, v0);
    __stcs(out + (size_t)1 * n4 + i, v1);
    __stcs(out + (size_t)2 * n4 + i, v2);
    __stcs(out + (size_t)3 * n4 + i, v3);
}

extern "C" void kernel_launch(void* const* d_in, const int* in_sizes, int n_in,
                              void* d_out, int out_size) {
    const float* x = (const float*)d_in[0];
    float* out = (float*)d_out;

    const int total = in_sizes[0];          // T*N = 33,554,432
    const int n = total / 4;                // N per timestep
    const int n4 = n / 4;                   // float4 groups per timestep = 2,097,152

    const int threads = 256;
    const int blocks = (n4 + threads - 1) / threads;   // 8192

    lif_kernel<<<blocks, threads>>>((const float4*)x, (float4*)out, n4);
}